// round 4
// baseline (speedup 1.0000x reference)
#include <cuda_runtime.h>
#include <cuda_bf16.h>

// out[b,d,n] = w[d] * in[b,d,n];  B=8, D=2048, N=2048, fp32.
// HBM-bound stream. R4: Blackwell 256-bit ld/st (v8.f32) to halve L1tex
// wavefront count; .cs hints reverted (proven neutral in R3).

static constexpr int B = 8;
static constexpr int D = 2048;
static constexpr int N = 2048;
static constexpr long long TOTAL8 = (long long)B * D * N / 8;  // 4,194,304 float8
static constexpr int THREADS = 256;
static constexpr int UNROLL  = 4;
static constexpr int BLOCK_ELEMS = THREADS * UNROLL;           // 1024 float8 / block

__device__ __forceinline__ void ldg_v8(const float* __restrict__ p, float* v) {
    asm volatile("ld.global.v8.f32 {%0,%1,%2,%3,%4,%5,%6,%7}, [%8];"
                 : "=f"(v[0]), "=f"(v[1]), "=f"(v[2]), "=f"(v[3]),
                   "=f"(v[4]), "=f"(v[5]), "=f"(v[6]), "=f"(v[7])
                 : "l"(p));
}

__device__ __forceinline__ void stg_v8(float* __restrict__ p, const float* v) {
    asm volatile("st.global.v8.f32 [%0], {%1,%2,%3,%4,%5,%6,%7,%8};"
                 :: "l"(p),
                    "f"(v[0]), "f"(v[1]), "f"(v[2]), "f"(v[3]),
                    "f"(v[4]), "f"(v[5]), "f"(v[6]), "f"(v[7])
                 : "memory");
}

__global__ void __launch_bounds__(THREADS)
channel_scale_kernel(const float* __restrict__ in,
                     const float* __restrict__ w,
                     float*       __restrict__ out)
{
    long long base = (long long)blockIdx.x * BLOCK_ELEMS + threadIdx.x;

    // Front-batch 4 independent 256-bit loads per thread (128B in flight).
    float v[UNROLL][8];
#pragma unroll
    for (int k = 0; k < UNROLL; k++) {
        long long i8 = base + (long long)k * THREADS;
        ldg_v8(in + i8 * 8, v[k]);
    }

#pragma unroll
    for (int k = 0; k < UNROLL; k++) {
        long long i8 = base + (long long)k * THREADS;
        // one float8 lies entirely within one channel row (8 | N):
        // d = (i8*8 / N) % D = (i8 >> 8) & 2047
        int d = (int)((i8 >> 8) & (D - 1));
        float s = __ldg(w + d);          // weights L2-resident (8 KB)
#pragma unroll
        for (int j = 0; j < 8; j++) v[k][j] *= s;
        stg_v8(out + i8 * 8, v[k]);
    }
}

extern "C" void kernel_launch(void* const* d_in, const int* in_sizes, int n_in,
                              void* d_out, int out_size)
{
    const float* in = (const float*)d_in[0];   // inputs [B, D, N] fp32
    const float* w  = (const float*)d_in[1];   // attention_weights [D] fp32
    float* out = (float*)d_out;

    long long blocks = TOTAL8 / BLOCK_ELEMS;   // 4096, exact cover
    channel_scale_kernel<<<(unsigned)blocks, THREADS>>>(in, w, out);
}